// round 1
// baseline (speedup 1.0000x reference)
#include <cuda_runtime.h>
#include <cuda_bf16.h>

#define NN   50000
#define NE   800000
#define FIN  128
#define HID  256
#define NG   128

// ---------------- device scratch (static allocation is allowed) -------------
__device__ float4 g_ax[NN * FIN / 4];   // spmm(x)            [N,128]
__device__ float4 g_h1[NN * HID / 4];   // relu(ax@W1+b1)     [N,256]
__device__ float4 g_t2[NN * HID / 4];   // h1@W2              [N,256]
__device__ float4 g_h2[NN * HID / 4];   // relu(spmm(t2)+b2)  [N,256]
__device__ int    g_deg[NN];
__device__ int    g_rp[NN + 1];
__device__ int    g_cursor[NN];
__device__ int    g_srcs[NE];
__device__ float  g_ws[NE];
__device__ float  g_pool[NG * HID];

// ---------------- CSR build -------------------------------------------------
__global__ void zero_kernel() {
    int i = blockIdx.x * blockDim.x + threadIdx.x;
    if (i < NN) g_deg[i] = 0;
    if (i < NG * HID) g_pool[i] = 0.0f;
}

__global__ void hist_kernel(const int* __restrict__ dst) {
    int e = blockIdx.x * blockDim.x + threadIdx.x;
    if (e < NE) atomicAdd(&g_deg[dst[e]], 1);
}

// single-block exclusive scan of g_deg -> g_rp (and g_cursor copy)
__global__ void scan_kernel() {
    __shared__ int warp_sums[32];
    __shared__ int s_carry;
    if (threadIdx.x == 0) s_carry = 0;
    __syncthreads();
    int lane = threadIdx.x & 31, w = threadIdx.x >> 5;
    for (int base = 0; base < NN; base += blockDim.x) {
        int idx = base + threadIdx.x;
        int v = (idx < NN) ? g_deg[idx] : 0;
        int incl = v;
        #pragma unroll
        for (int o = 1; o < 32; o <<= 1) {
            int t = __shfl_up_sync(0xffffffffu, incl, o);
            if (lane >= o) incl += t;
        }
        if (lane == 31) warp_sums[w] = incl;
        __syncthreads();
        if (w == 0) {
            int s = warp_sums[lane];
            #pragma unroll
            for (int o = 1; o < 32; o <<= 1) {
                int t = __shfl_up_sync(0xffffffffu, s, o);
                if (lane >= o) s += t;
            }
            warp_sums[lane] = s;
        }
        __syncthreads();
        int warp_off = (w > 0) ? warp_sums[w - 1] : 0;
        int excl = s_carry + warp_off + incl - v;
        if (idx < NN) { g_rp[idx] = excl; g_cursor[idx] = excl; }
        __syncthreads();
        if (threadIdx.x == blockDim.x - 1) s_carry = s_carry + warp_off + incl;
        __syncthreads();
    }
    if (threadIdx.x == 0) g_rp[NN] = s_carry;
}

__global__ void fill_kernel(const int* __restrict__ src, const int* __restrict__ dst,
                            const float* __restrict__ ew) {
    int e = blockIdx.x * blockDim.x + threadIdx.x;
    if (e < NE) {
        int p = atomicAdd(&g_cursor[dst[e]], 1);
        g_srcs[p] = src[e];
        g_ws[p]   = ew[e];
    }
}

// ---------------- SPMM (warp per dst node, gather-reduce) -------------------
__global__ void __launch_bounds__(256) spmm128_kernel(const float4* __restrict__ x4) {
    int warp = (blockIdx.x * blockDim.x + threadIdx.x) >> 5;
    int lane = threadIdx.x & 31;
    if (warp >= NN) return;
    int e0 = g_rp[warp], e1 = g_rp[warp + 1];
    float4 acc = make_float4(0.f, 0.f, 0.f, 0.f);
    for (int e = e0; e < e1; e++) {
        int   s = g_srcs[e];
        float w = g_ws[e];
        float4 v = __ldg(&x4[s * (FIN / 4) + lane]);
        acc.x += w * v.x; acc.y += w * v.y; acc.z += w * v.z; acc.w += w * v.w;
    }
    g_ax[warp * (FIN / 4) + lane] = acc;
}

__global__ void __launch_bounds__(256) spmm256_kernel(const float* __restrict__ b2) {
    int warp = (blockIdx.x * blockDim.x + threadIdx.x) >> 5;
    int lane = threadIdx.x & 31;
    if (warp >= NN) return;
    int e0 = g_rp[warp], e1 = g_rp[warp + 1];
    float4 a0 = make_float4(0.f, 0.f, 0.f, 0.f);
    float4 a1 = make_float4(0.f, 0.f, 0.f, 0.f);
    for (int e = e0; e < e1; e++) {
        int   s = g_srcs[e];
        float w = g_ws[e];
        const float4* row = &g_t2[s * (HID / 4)];
        float4 v0 = __ldg(&row[lane]);
        float4 v1 = __ldg(&row[lane + 32]);
        a0.x += w * v0.x; a0.y += w * v0.y; a0.z += w * v0.z; a0.w += w * v0.w;
        a1.x += w * v1.x; a1.y += w * v1.y; a1.z += w * v1.z; a1.w += w * v1.w;
    }
    const float4* b4 = (const float4*)b2;
    float4 c0 = __ldg(&b4[lane]);
    float4 c1 = __ldg(&b4[lane + 32]);
    a0.x = fmaxf(a0.x + c0.x, 0.f); a0.y = fmaxf(a0.y + c0.y, 0.f);
    a0.z = fmaxf(a0.z + c0.z, 0.f); a0.w = fmaxf(a0.w + c0.w, 0.f);
    a1.x = fmaxf(a1.x + c1.x, 0.f); a1.y = fmaxf(a1.y + c1.y, 0.f);
    a1.z = fmaxf(a1.z + c1.z, 0.f); a1.w = fmaxf(a1.w + c1.w, 0.f);
    g_h2[warp * (HID / 4) + lane]      = a0;
    g_h2[warp * (HID / 4) + lane + 32] = a1;
}

// ---------------- fp32 tiled GEMM: C = A[M,K] @ W[K,N] (+bias, relu) --------
#define BM 128
#define BN 128
#define BK 16

__global__ void __launch_bounds__(256) gemm_kernel(
    const float* __restrict__ A, const float* __restrict__ W,
    const float* __restrict__ bias, float* __restrict__ C,
    int M, int N, int K, int doBiasRelu)
{
    __shared__ float As[BK][BM];
    __shared__ float Bs[BK][BN];
    int tid = threadIdx.x;
    int tx = tid & 15, ty = tid >> 4;
    int bm0 = blockIdx.x * BM, bn0 = blockIdx.y * BN;

    float acc[8][8];
    #pragma unroll
    for (int i = 0; i < 8; i++)
        #pragma unroll
        for (int j = 0; j < 8; j++) acc[i][j] = 0.f;

    for (int k0 = 0; k0 < K; k0 += BK) {
        // load A tile (128x16), transposed into As[k][m]
        #pragma unroll
        for (int i = 0; i < 2; i++) {
            int idx = tid + i * 256;          // 0..511
            int r = idx >> 2, c4 = idx & 3;   // r:0..127, c4:0..3
            float4 v = make_float4(0.f, 0.f, 0.f, 0.f);
            if (bm0 + r < M)
                v = *(const float4*)&A[(size_t)(bm0 + r) * K + k0 + c4 * 4];
            As[c4 * 4 + 0][r] = v.x;
            As[c4 * 4 + 1][r] = v.y;
            As[c4 * 4 + 2][r] = v.z;
            As[c4 * 4 + 3][r] = v.w;
        }
        // load B tile (16x128)
        #pragma unroll
        for (int i = 0; i < 2; i++) {
            int idx = tid + i * 256;          // 0..511
            int r = idx >> 5, c4 = idx & 31;  // r:0..15, c4:0..31
            float4 v = *(const float4*)&W[(size_t)(k0 + r) * N + bn0 + c4 * 4];
            *(float4*)&Bs[r][c4 * 4] = v;
        }
        __syncthreads();
        #pragma unroll
        for (int kk = 0; kk < BK; kk++) {
            float a[8], b[8];
            *(float4*)&a[0] = *(float4*)&As[kk][ty * 8];
            *(float4*)&a[4] = *(float4*)&As[kk][ty * 8 + 4];
            *(float4*)&b[0] = *(float4*)&Bs[kk][tx * 8];
            *(float4*)&b[4] = *(float4*)&Bs[kk][tx * 8 + 4];
            #pragma unroll
            for (int i = 0; i < 8; i++)
                #pragma unroll
                for (int j = 0; j < 8; j++)
                    acc[i][j] += a[i] * b[j];
        }
        __syncthreads();
    }
    // epilogue
    #pragma unroll
    for (int i = 0; i < 8; i++) {
        int row = bm0 + ty * 8 + i;
        if (row >= M) continue;
        #pragma unroll
        for (int j = 0; j < 8; j += 4) {
            int col = bn0 + tx * 8 + j;
            float4 v;
            v.x = acc[i][j]; v.y = acc[i][j + 1]; v.z = acc[i][j + 2]; v.w = acc[i][j + 3];
            if (doBiasRelu) {
                v.x = fmaxf(v.x + bias[col],     0.f);
                v.y = fmaxf(v.y + bias[col + 1], 0.f);
                v.z = fmaxf(v.z + bias[col + 2], 0.f);
                v.w = fmaxf(v.w + bias[col + 3], 0.f);
            }
            *(float4*)&C[(size_t)row * N + col] = v;
        }
    }
}

// ---------------- pooling (seg_ids sorted) ----------------------------------
#define POOL_ROWS 512
__global__ void __launch_bounds__(256) pool_kernel(const int* __restrict__ seg) {
    __shared__ int segs[POOL_ROWS];
    int r0 = blockIdx.x * POOL_ROWS;
    int nr = min(POOL_ROWS, NN - r0);
    if (nr <= 0) return;
    for (int r = threadIdx.x; r < nr; r += blockDim.x) segs[r] = seg[r0 + r];
    __syncthreads();
    int col = threadIdx.x;  // 256 cols
    const float* h2 = (const float*)g_h2;
    float acc = 0.f;
    int cur = segs[0];
    for (int r = 0; r < nr; r++) {
        int s = segs[r];
        if (s != cur) { atomicAdd(&g_pool[cur * HID + col], acc); acc = 0.f; cur = s; }
        acc += h2[(size_t)(r0 + r) * HID + col];
    }
    atomicAdd(&g_pool[cur * HID + col], acc);
}

// ---------------- head: out = relu(g@Wd+bd) @ Wo + bo -----------------------
__global__ void __launch_bounds__(256) head_kernel(
    const float* __restrict__ Wd, const float* __restrict__ bd,
    const float* __restrict__ Wo, const float* __restrict__ bo,
    float* __restrict__ out)
{
    __shared__ float grow[HID];
    __shared__ float red[HID];
    int i = blockIdx.x, t = threadIdx.x;
    grow[t] = g_pool[i * HID + t];
    __syncthreads();
    float acc = bd[t];
    #pragma unroll 8
    for (int k = 0; k < HID; k++) acc += grow[k] * Wd[k * HID + t];
    acc = fmaxf(acc, 0.f);
    red[t] = acc * Wo[t];
    __syncthreads();
    for (int s = 128; s > 0; s >>= 1) {
        if (t < s) red[t] += red[t + s];
        __syncthreads();
    }
    if (t == 0) out[i] = red[0] + bo[0];
}

// ---------------- launch ----------------------------------------------------
extern "C" void kernel_launch(void* const* d_in, const int* in_sizes, int n_in,
                              void* d_out, int out_size)
{
    const float* x   = (const float*)d_in[0];
    const int*   esr = (const int*)  d_in[1];
    const int*   eds = (const int*)  d_in[2];
    const float* ew  = (const float*)d_in[3];
    const int*   seg = (const int*)  d_in[4];
    const float* W1  = (const float*)d_in[5];
    const float* b1  = (const float*)d_in[6];
    const float* W2  = (const float*)d_in[7];
    const float* b2  = (const float*)d_in[8];
    const float* Wd  = (const float*)d_in[9];
    const float* bd  = (const float*)d_in[10];
    const float* Wo  = (const float*)d_in[11];
    const float* bo  = (const float*)d_in[12];
    float* out = (float*)d_out;

    void *p_ax, *p_h1, *p_t2;
    cudaGetSymbolAddress(&p_ax, g_ax);
    cudaGetSymbolAddress(&p_h1, g_h1);
    cudaGetSymbolAddress(&p_t2, g_t2);

    // 1) zero counters + pool accumulator
    zero_kernel<<<(NN + 255) / 256, 256>>>();
    // 2) CSR build
    hist_kernel<<<(NE + 255) / 256, 256>>>(eds);
    scan_kernel<<<1, 1024>>>();
    fill_kernel<<<(NE + 255) / 256, 256>>>(esr, eds, ew);
    // 3) spmm(x) -> ax  [N,128]
    spmm128_kernel<<<NN / 8, 256>>>((const float4*)x);
    // 4) h1 = relu(ax @ W1 + b1)
    {
        dim3 grid((NN + BM - 1) / BM, HID / BN);
        gemm_kernel<<<grid, 256>>>((const float*)p_ax, W1, b1, (float*)p_h1,
                                   NN, HID, FIN, 1);
    }
    // 5) t2 = h1 @ W2
    {
        dim3 grid((NN + BM - 1) / BM, HID / BN);
        gemm_kernel<<<grid, 256>>>((const float*)p_h1, W2, b1 /*unused*/, (float*)p_t2,
                                   NN, HID, HID, 0);
    }
    // 6) h2 = relu(spmm(t2) + b2)
    spmm256_kernel<<<NN / 8, 256>>>(b2);
    // 7) pool
    pool_kernel<<<(NN + POOL_ROWS - 1) / POOL_ROWS, 256>>>(seg);
    // 8) head
    head_kernel<<<NG, HID>>>(Wd, bd, Wo, bo, out);
}

// round 3
// speedup vs baseline: 1.3077x; 1.3077x over previous
#include <cuda_runtime.h>
#include <cuda_bf16.h>
#include <cstdint>

#define NN   50000
#define NE   800000
#define FIN  128
#define HID  256
#define NG   128

// ---------------- device scratch (static allocation is allowed) -------------
__device__ float4 g_ax[NN * FIN / 4];   // spmm(x)            [N,128]
__device__ float4 g_h1[NN * HID / 4];   // relu(ax@W1+b1)     [N,256]
__device__ float4 g_t2[NN * HID / 4];   // h1@W2              [N,256]
__device__ float4 g_h2[NN * HID / 4];   // relu(spmm(t2)+b2)  [N,256]
__device__ int    g_deg[NN];
__device__ int    g_rp[NN + 1];
__device__ int    g_cursor[NN];
__device__ int    g_srcs[NE];
__device__ float  g_ws[NE];
__device__ float  g_pool[NG * HID];

// ---------------- CSR build -------------------------------------------------
__global__ void zero_kernel() {
    int i = blockIdx.x * blockDim.x + threadIdx.x;
    if (i < NN) g_deg[i] = 0;
    if (i < NG * HID) g_pool[i] = 0.0f;
}

__global__ void hist_kernel(const int* __restrict__ dst) {
    int e = blockIdx.x * blockDim.x + threadIdx.x;
    if (e < NE) atomicAdd(&g_deg[dst[e]], 1);
}

// single-block exclusive scan of g_deg -> g_rp (and g_cursor copy)
__global__ void scan_kernel() {
    __shared__ int warp_sums[32];
    __shared__ int s_carry;
    if (threadIdx.x == 0) s_carry = 0;
    __syncthreads();
    int lane = threadIdx.x & 31, w = threadIdx.x >> 5;
    for (int base = 0; base < NN; base += blockDim.x) {
        int idx = base + threadIdx.x;
        int v = (idx < NN) ? g_deg[idx] : 0;
        int incl = v;
        #pragma unroll
        for (int o = 1; o < 32; o <<= 1) {
            int t = __shfl_up_sync(0xffffffffu, incl, o);
            if (lane >= o) incl += t;
        }
        if (lane == 31) warp_sums[w] = incl;
        __syncthreads();
        if (w == 0) {
            int s = warp_sums[lane];
            #pragma unroll
            for (int o = 1; o < 32; o <<= 1) {
                int t = __shfl_up_sync(0xffffffffu, s, o);
                if (lane >= o) s += t;
            }
            warp_sums[lane] = s;
        }
        __syncthreads();
        int warp_off = (w > 0) ? warp_sums[w - 1] : 0;
        int excl = s_carry + warp_off + incl - v;
        if (idx < NN) { g_rp[idx] = excl; g_cursor[idx] = excl; }
        __syncthreads();
        if (threadIdx.x == blockDim.x - 1) s_carry = s_carry + warp_off + incl;
        __syncthreads();
    }
    if (threadIdx.x == 0) g_rp[NN] = s_carry;
}

__global__ void fill_kernel(const int* __restrict__ src, const int* __restrict__ dst,
                            const float* __restrict__ ew) {
    int e = blockIdx.x * blockDim.x + threadIdx.x;
    if (e < NE) {
        int p = atomicAdd(&g_cursor[dst[e]], 1);
        g_srcs[p] = src[e];
        g_ws[p]   = ew[e];
    }
}

// ---------------- SPMM (warp per dst node, gather-reduce) -------------------
__global__ void __launch_bounds__(256) spmm128_kernel(const float4* __restrict__ x4) {
    int warp = (blockIdx.x * blockDim.x + threadIdx.x) >> 5;
    int lane = threadIdx.x & 31;
    if (warp >= NN) return;
    int e0 = g_rp[warp], e1 = g_rp[warp + 1];
    float4 acc = make_float4(0.f, 0.f, 0.f, 0.f);
    for (int e = e0; e < e1; e++) {
        int   s = g_srcs[e];
        float w = g_ws[e];
        float4 v = __ldg(&x4[s * (FIN / 4) + lane]);
        acc.x += w * v.x; acc.y += w * v.y; acc.z += w * v.z; acc.w += w * v.w;
    }
    g_ax[warp * (FIN / 4) + lane] = acc;
}

__global__ void __launch_bounds__(256) spmm256_kernel(const float* __restrict__ b2) {
    int warp = (blockIdx.x * blockDim.x + threadIdx.x) >> 5;
    int lane = threadIdx.x & 31;
    if (warp >= NN) return;
    int e0 = g_rp[warp], e1 = g_rp[warp + 1];
    float4 a0 = make_float4(0.f, 0.f, 0.f, 0.f);
    float4 a1 = make_float4(0.f, 0.f, 0.f, 0.f);
    for (int e = e0; e < e1; e++) {
        int   s = g_srcs[e];
        float w = g_ws[e];
        const float4* row = &g_t2[s * (HID / 4)];
        float4 v0 = __ldg(&row[lane]);
        float4 v1 = __ldg(&row[lane + 32]);
        a0.x += w * v0.x; a0.y += w * v0.y; a0.z += w * v0.z; a0.w += w * v0.w;
        a1.x += w * v1.x; a1.y += w * v1.y; a1.z += w * v1.z; a1.w += w * v1.w;
    }
    const float4* b4 = (const float4*)b2;
    float4 c0 = __ldg(&b4[lane]);
    float4 c1 = __ldg(&b4[lane + 32]);
    a0.x = fmaxf(a0.x + c0.x, 0.f); a0.y = fmaxf(a0.y + c0.y, 0.f);
    a0.z = fmaxf(a0.z + c0.z, 0.f); a0.w = fmaxf(a0.w + c0.w, 0.f);
    a1.x = fmaxf(a1.x + c1.x, 0.f); a1.y = fmaxf(a1.y + c1.y, 0.f);
    a1.z = fmaxf(a1.z + c1.z, 0.f); a1.w = fmaxf(a1.w + c1.w, 0.f);
    g_h2[warp * (HID / 4) + lane]      = a0;
    g_h2[warp * (HID / 4) + lane + 32] = a1;
}

// ---------------- tf32 tensor-core GEMM: C = A[M,K] @ W[K,N] (+bias, relu) --
// Block tile 128x128, BK=16. 8 warps, each 32(m) x 64(n) via m16n8k8 tf32 mma.
// Smem row stride 136 floats => (8k+m)%32 bank mapping is bijective for the
// fragment load patterns (k<4 or k in 4..7, m<8) -> conflict-free LDS.
#define GBM 128
#define GBN 128
#define GBK 16
#define SSTRIDE 136

__device__ __forceinline__ uint32_t f2tf32(float x) {
    uint32_t u;
    asm("cvt.rna.tf32.f32 %0, %1;" : "=r"(u) : "f"(x));
    return u;
}

__global__ void __launch_bounds__(256) gemm_tf32_kernel(
    const float* __restrict__ A, const float* __restrict__ W,
    const float* __restrict__ bias, float* __restrict__ C,
    int M, int N, int K, int doBiasRelu)
{
    __shared__ uint32_t As[GBK][SSTRIDE];   // [k][m], tf32 bits
    __shared__ uint32_t Bs[GBK][SSTRIDE];   // [k][n], tf32 bits

    int tid  = threadIdx.x;
    int lane = tid & 31;
    int warp = tid >> 5;              // 0..7
    int warp_m = warp & 3;            // 0..3  -> row base 32*warp_m
    int warp_n = warp >> 2;           // 0..1  -> col base 64*warp_n
    int gid = lane >> 2;              // 0..7
    int tg  = lane & 3;               // 0..3

    int bm0 = blockIdx.x * GBM;
    int bn0 = blockIdx.y * GBN;

    float c[2][8][4];
    #pragma unroll
    for (int mt = 0; mt < 2; mt++)
        #pragma unroll
        for (int nt = 0; nt < 8; nt++)
            #pragma unroll
            for (int r = 0; r < 4; r++) c[mt][nt][r] = 0.f;

    for (int k0 = 0; k0 < K; k0 += GBK) {
        // A tile: 128 rows x 16 cols = 512 float4; transpose into As[k][m]
        #pragma unroll
        for (int i = 0; i < 2; i++) {
            int idx = tid + i * 256;
            int r = idx >> 2, c4 = idx & 3;
            float4 v = make_float4(0.f, 0.f, 0.f, 0.f);
            if (bm0 + r < M)
                v = *(const float4*)&A[(size_t)(bm0 + r) * K + k0 + c4 * 4];
            As[c4 * 4 + 0][r] = f2tf32(v.x);
            As[c4 * 4 + 1][r] = f2tf32(v.y);
            As[c4 * 4 + 2][r] = f2tf32(v.z);
            As[c4 * 4 + 3][r] = f2tf32(v.w);
        }
        // B tile: 16 rows x 128 cols
        #pragma unroll
        for (int i = 0; i < 2; i++) {
            int idx = tid + i * 256;
            int r = idx >> 5, c4 = idx & 31;
            float4 v = *(const float4*)&W[(size_t)(k0 + r) * N + bn0 + c4 * 4];
            Bs[r][c4 * 4 + 0] = f2tf32(v.x);
            Bs[r][c4 * 4 + 1] = f2tf32(v.y);
            Bs[r][c4 * 4 + 2] = f2tf32(v.z);
            Bs[r][c4 * 4 + 3] = f2tf32(v.w);
        }
        __syncthreads();

        #pragma unroll
        for (int ks = 0; ks < 2; ks++) {
            int kb = ks * 8;
            uint32_t a[2][4], b[8][2];
            #pragma unroll
            for (int mt = 0; mt < 2; mt++) {
                int mr = warp_m * 32 + mt * 16;
                a[mt][0] = As[kb + tg    ][mr + gid    ];
                a[mt][1] = As[kb + tg    ][mr + gid + 8];
                a[mt][2] = As[kb + tg + 4][mr + gid    ];
                a[mt][3] = As[kb + tg + 4][mr + gid + 8];
            }
            #pragma unroll
            for (int nt = 0; nt < 8; nt++) {
                int nc = warp_n * 64 + nt * 8;
                b[nt][0] = Bs[kb + tg    ][nc + gid];
                b[nt][1] = Bs[kb + tg + 4][nc + gid];
            }
            #pragma unroll
            for (int mt = 0; mt < 2; mt++)
                #pragma unroll
                for (int nt = 0; nt < 8; nt++) {
                    asm volatile(
                        "mma.sync.aligned.m16n8k8.row.col.f32.tf32.tf32.f32 "
                        "{%0,%1,%2,%3}, {%4,%5,%6,%7}, {%8,%9}, {%0,%1,%2,%3};"
                        : "+f"(c[mt][nt][0]), "+f"(c[mt][nt][1]),
                          "+f"(c[mt][nt][2]), "+f"(c[mt][nt][3])
                        : "r"(a[mt][0]), "r"(a[mt][1]), "r"(a[mt][2]), "r"(a[mt][3]),
                          "r"(b[nt][0]), "r"(b[nt][1]));
                }
        }
        __syncthreads();
    }

    // epilogue: c0/c1 at (row=gid, col=2tg,2tg+1), c2/c3 at row=gid+8
    #pragma unroll
    for (int mt = 0; mt < 2; mt++) {
        int rbase = bm0 + warp_m * 32 + mt * 16 + gid;
        #pragma unroll
        for (int nt = 0; nt < 8; nt++) {
            int col = bn0 + warp_n * 64 + nt * 8 + 2 * tg;
            float v0 = c[mt][nt][0], v1 = c[mt][nt][1];
            float v2 = c[mt][nt][2], v3 = c[mt][nt][3];
            if (doBiasRelu) {
                float bb0 = bias[col], bb1 = bias[col + 1];
                v0 = fmaxf(v0 + bb0, 0.f); v1 = fmaxf(v1 + bb1, 0.f);
                v2 = fmaxf(v2 + bb0, 0.f); v3 = fmaxf(v3 + bb1, 0.f);
            }
            if (rbase < M)     *(float2*)&C[(size_t)rbase * N + col]       = make_float2(v0, v1);
            if (rbase + 8 < M) *(float2*)&C[(size_t)(rbase + 8) * N + col] = make_float2(v2, v3);
        }
    }
}

// ---------------- pooling (seg_ids sorted) ----------------------------------
#define POOL_ROWS 512
__global__ void __launch_bounds__(256) pool_kernel(const int* __restrict__ seg) {
    __shared__ int segs[POOL_ROWS];
    int r0 = blockIdx.x * POOL_ROWS;
    int nr = min(POOL_ROWS, NN - r0);
    if (nr <= 0) return;
    for (int r = threadIdx.x; r < nr; r += blockDim.x) segs[r] = seg[r0 + r];
    __syncthreads();
    int col = threadIdx.x;  // 256 cols
    const float* h2 = (const float*)g_h2;
    float acc = 0.f;
    int cur = segs[0];
    for (int r = 0; r < nr; r++) {
        int s = segs[r];
        if (s != cur) { atomicAdd(&g_pool[cur * HID + col], acc); acc = 0.f; cur = s; }
        acc += h2[(size_t)(r0 + r) * HID + col];
    }
    atomicAdd(&g_pool[cur * HID + col], acc);
}

// ---------------- head: out = relu(g@Wd+bd) @ Wo + bo -----------------------
__global__ void __launch_bounds__(256) head_kernel(
    const float* __restrict__ Wd, const float* __restrict__ bd,
    const float* __restrict__ Wo, const float* __restrict__ bo,
    float* __restrict__ out)
{
    __shared__ float grow[HID];
    __shared__ float red[HID];
    int i = blockIdx.x, t = threadIdx.x;
    grow[t] = g_pool[i * HID + t];
    __syncthreads();
    float acc = bd[t];
    #pragma unroll 8
    for (int k = 0; k < HID; k++) acc += grow[k] * Wd[k * HID + t];
    acc = fmaxf(acc, 0.f);
    red[t] = acc * Wo[t];
    __syncthreads();
    for (int s = 128; s > 0; s >>= 1) {
        if (t < s) red[t] += red[t + s];
        __syncthreads();
    }
    if (t == 0) out[i] = red[0] + bo[0];
}

// ---------------- launch ----------------------------------------------------
extern "C" void kernel_launch(void* const* d_in, const int* in_sizes, int n_in,
                              void* d_out, int out_size)
{
    const float* x   = (const float*)d_in[0];
    const int*   esr = (const int*)  d_in[1];
    const int*   eds = (const int*)  d_in[2];
    const float* ew  = (const float*)d_in[3];
    const int*   seg = (const int*)  d_in[4];
    const float* W1  = (const float*)d_in[5];
    const float* b1  = (const float*)d_in[6];
    const float* W2  = (const float*)d_in[7];
    const float* b2  = (const float*)d_in[8];
    const float* Wd  = (const float*)d_in[9];
    const float* bd  = (const float*)d_in[10];
    const float* Wo  = (const float*)d_in[11];
    const float* bo  = (const float*)d_in[12];
    float* out = (float*)d_out;

    void *p_ax, *p_h1, *p_t2;
    cudaGetSymbolAddress(&p_ax, g_ax);
    cudaGetSymbolAddress(&p_h1, g_h1);
    cudaGetSymbolAddress(&p_t2, g_t2);

    // 1) zero counters + pool accumulator
    zero_kernel<<<(NN + 255) / 256, 256>>>();
    // 2) CSR build
    hist_kernel<<<(NE + 255) / 256, 256>>>(eds);
    scan_kernel<<<1, 1024>>>();
    fill_kernel<<<(NE + 255) / 256, 256>>>(esr, eds, ew);
    // 3) spmm(x) -> ax  [N,128]
    spmm128_kernel<<<NN / 8, 256>>>((const float4*)x);
    // 4) h1 = relu(ax @ W1 + b1)
    {
        dim3 grid((NN + GBM - 1) / GBM, HID / GBN);
        gemm_tf32_kernel<<<grid, 256>>>((const float*)p_ax, W1, b1, (float*)p_h1,
                                        NN, HID, FIN, 1);
    }
    // 5) t2 = h1 @ W2
    {
        dim3 grid((NN + GBM - 1) / GBM, HID / GBN);
        gemm_tf32_kernel<<<grid, 256>>>((const float*)p_h1, W2, b1 /*unused*/, (float*)p_t2,
                                        NN, HID, HID, 0);
    }
    // 6) h2 = relu(spmm(t2) + b2)
    spmm256_kernel<<<NN / 8, 256>>>(b2);
    // 7) pool
    pool_kernel<<<(NN + POOL_ROWS - 1) / POOL_ROWS, 256>>>(seg);
    // 8) head
    head_kernel<<<NG, HID>>>(Wd, bd, Wo, bo, out);
}